// round 2
// baseline (speedup 1.0000x reference)
#include <cuda_runtime.h>
#include <cuda_bf16.h>
#include <math.h>
#include <stdint.h>

// ---------------------------------------------------------------------------
// ConvTokenEmbedder: char CNN + highway x2 + projection
// Round 2: bf16x3 split tensor-core GEMMs (mma.sync) + de-spilled conv
// ---------------------------------------------------------------------------

#define NTOK   4096
#define NFILT  2048
#define PROJ   512
#define MAXC   50
#define CDIM   16
#define KDIM   2048          // GEMM K (all three GEMMs)

// Scratch (static device globals; no runtime allocation allowed)
__device__ float g_h[NTOK * NFILT];               // 32 MB fp32 h
__device__ float g_p[NTOK * 2 * NFILT];           // 64 MB fp32 highway pre-act
__device__ __nv_bfloat16 g_hhi[NTOK * NFILT];     // h split
__device__ __nv_bfloat16 g_hlo[NTOK * NFILT];
__device__ __nv_bfloat16 g_w0hi[2 * NFILT * NFILT];
__device__ __nv_bfloat16 g_w0lo[2 * NFILT * NFILT];
__device__ __nv_bfloat16 g_w1hi[2 * NFILT * NFILT];
__device__ __nv_bfloat16 g_w1lo[2 * NFILT * NFILT];
__device__ __nv_bfloat16 g_wphi[PROJ * NFILT];
__device__ __nv_bfloat16 g_wplo[PROJ * NFILT];

// ---------------------------------------------------------------------------
// Conv stage — time-chunked accumulators (<=25 regs) to avoid local spills
// ---------------------------------------------------------------------------
template <int W>
__device__ __forceinline__ float conv_max(const float* __restrict__ xs,
                                          const float* __restrict__ wg,
                                          float bias) {
    constexpr int NT = 51 - W;           // valid time positions
    constexpr int TC = (NT + 1) / 2;     // chunk size (two overlapping chunks)
    float best = -3.4e38f;
#pragma unroll
    for (int ch = 0; ch < 2; ch++) {
        const int t0 = (ch == 0) ? 0 : (NT - TC);
        float acc[TC];
#pragma unroll
        for (int t = 0; t < TC; t++) acc[t] = 0.0f;
#pragma unroll 2
        for (int c = 0; c < CDIM; c++) {
            float wr[W];
#pragma unroll
            for (int k = 0; k < W; k++) wr[k] = wg[c * W + k];
#pragma unroll
            for (int j = 0; j < TC + W - 1; j++) {
                float xv = xs[c * 51 + t0 + j];
#pragma unroll
                for (int k = 0; k < W; k++) {
                    int t = j - k;                 // compile-time after unroll
                    if (t >= 0 && t < TC) acc[t] = fmaf(xv, wr[k], acc[t]);
                }
            }
        }
#pragma unroll
        for (int t = 0; t < TC; t++) best = fmaxf(best, acc[t]);
    }
    best += bias;
    return fmaxf(best, 0.0f);
}

__global__ __launch_bounds__(256)
void conv_kernel(const int*   __restrict__ chars,
                 const float* __restrict__ emb,
                 const float* __restrict__ w0, const float* __restrict__ b0,
                 const float* __restrict__ w1, const float* __restrict__ b1,
                 const float* __restrict__ w2, const float* __restrict__ b2,
                 const float* __restrict__ w3, const float* __restrict__ b3,
                 const float* __restrict__ w4, const float* __restrict__ b4,
                 const float* __restrict__ w5, const float* __restrict__ b5,
                 const float* __restrict__ w6, const float* __restrict__ b6,
                 float* __restrict__ h) {
    __shared__ float xs[CDIM * 51];
    __shared__ int   chs[MAXC];

    const int n   = blockIdx.x;
    const int tid = threadIdx.x;

    if (tid < MAXC) chs[tid] = chars[n * MAXC + tid];
    __syncthreads();
    for (int idx = tid; idx < MAXC * CDIM; idx += 256) {
        int t = idx >> 4;
        int c = idx & 15;
        xs[c * 51 + t] = emb[chs[t] * CDIM + c];
    }
    __syncthreads();

    float* hrow = h + (size_t)n * NFILT;

    // warp-uniform widths
    {
        int f = tid;
        float r;
        if (f < 32)        r = conv_max<1>(xs, w0 + f * (CDIM * 1),        b0[f]);
        else if (f < 64)   r = conv_max<2>(xs, w1 + (f - 32) * (CDIM * 2), b1[f - 32]);
        else if (f < 128)  r = conv_max<3>(xs, w2 + (f - 64) * (CDIM * 3), b2[f - 64]);
        else               r = conv_max<4>(xs, w3 + (f - 128) * (CDIM * 4), b3[f - 128]);
        hrow[f] = r;
    }
    {
        int f = tid + 256;
        hrow[f] = conv_max<5>(xs, w4 + (f - 256) * (CDIM * 5), b4[f - 256]);
    }
#pragma unroll
    for (int i = 2; i < 4; i++) {
        int f = tid + i * 256;
        hrow[f] = conv_max<6>(xs, w5 + (f - 512) * (CDIM * 6), b5[f - 512]);
    }
#pragma unroll
    for (int i = 4; i < 8; i++) {
        int f = tid + i * 256;
        hrow[f] = conv_max<7>(xs, w6 + (f - 1024) * (CDIM * 7), b6[f - 1024]);
    }
}

// ---------------------------------------------------------------------------
// fp32 -> (bf16 hi, bf16 lo) split
// ---------------------------------------------------------------------------
__global__ __launch_bounds__(256)
void cvt_split(const float* __restrict__ x,
               __nv_bfloat16* __restrict__ hi,
               __nv_bfloat16* __restrict__ lo, int n4) {
    int i = blockIdx.x * blockDim.x + threadIdx.x;
    if (i >= n4) return;
    float4 v = ((const float4*)x)[i];
    __nv_bfloat16 h0 = __float2bfloat16(v.x);
    __nv_bfloat16 h1 = __float2bfloat16(v.y);
    __nv_bfloat16 h2 = __float2bfloat16(v.z);
    __nv_bfloat16 h3 = __float2bfloat16(v.w);
    __nv_bfloat16 l0 = __float2bfloat16(v.x - __bfloat162float(h0));
    __nv_bfloat16 l1 = __float2bfloat16(v.y - __bfloat162float(h1));
    __nv_bfloat16 l2 = __float2bfloat16(v.z - __bfloat162float(h2));
    __nv_bfloat16 l3 = __float2bfloat16(v.w - __bfloat162float(h3));
    __nv_bfloat162* hp = (__nv_bfloat162*)hi;
    __nv_bfloat162* lp = (__nv_bfloat162*)lo;
    hp[i * 2 + 0] = __halves2bfloat162(h0, h1);
    hp[i * 2 + 1] = __halves2bfloat162(h2, h3);
    lp[i * 2 + 0] = __halves2bfloat162(l0, l1);
    lp[i * 2 + 1] = __halves2bfloat162(l2, l3);
}

// ---------------------------------------------------------------------------
// bf16x3 tensor GEMM (TN): C[m,n] = sum_k A[m,:]B[n,:] + bias[n]
//   fused split passes: seg0 hi*hi, seg1 hi*lo, seg2 lo*hi  (K' = 3*2048)
//   128x128x32 tile, 256 thr, warps 4(m) x 2(n), warp tile 32x64
//   mma.sync.m16n8k16 bf16, fp32 accum; ldmatrix from padded smem (stride 40)
// ---------------------------------------------------------------------------
#define GSTR 40              // smem row stride in bf16 elements (80B)
#define GITERS (3 * KDIM / 32)

__device__ __forceinline__ void ldm_x4(uint32_t addr, uint32_t& r0, uint32_t& r1,
                                       uint32_t& r2, uint32_t& r3) {
    asm volatile("ldmatrix.sync.aligned.m8n8.x4.shared.b16 {%0,%1,%2,%3}, [%4];"
                 : "=r"(r0), "=r"(r1), "=r"(r2), "=r"(r3) : "r"(addr));
}

__device__ __forceinline__ void mma16816(float* c, const uint32_t* a,
                                         uint32_t b0, uint32_t b1) {
    asm volatile(
        "mma.sync.aligned.m16n8k16.row.col.f32.bf16.bf16.f32 "
        "{%0,%1,%2,%3}, {%4,%5,%6,%7}, {%8,%9}, {%0,%1,%2,%3};"
        : "+f"(c[0]), "+f"(c[1]), "+f"(c[2]), "+f"(c[3])
        : "r"(a[0]), "r"(a[1]), "r"(a[2]), "r"(a[3]), "r"(b0), "r"(b1));
}

__global__ __launch_bounds__(256, 2)
void gemm_bf16x3(const __nv_bfloat16* __restrict__ Ahi,
                 const __nv_bfloat16* __restrict__ Alo,
                 const __nv_bfloat16* __restrict__ Bhi,
                 const __nv_bfloat16* __restrict__ Blo,
                 const float* __restrict__ bias,
                 float* __restrict__ C, int M, int N) {
    __shared__ __nv_bfloat16 As[2][128 * GSTR];
    __shared__ __nv_bfloat16 Bs[2][128 * GSTR];

    const int tid  = threadIdx.x;
    const int lane = tid & 31;
    const int warp = tid >> 5;
    const int wm   = warp & 3;        // 4 m-warps
    const int wn   = warp >> 2;       // 2 n-warps
    const int bm   = blockIdx.y * 128;
    const int bn   = blockIdx.x * 128;

    // global-load mapping: 2 chunks of 16B per matrix per thread
    const int lrow = tid >> 2;        // 0..63
    const int lcc  = tid & 3;         // 0..3 (16B chunk within 32-col row)
    const int soff0 = lrow * GSTR + lcc * 8;
    const int soff1 = (lrow + 64) * GSTR + lcc * 8;

    // ldmatrix lane addressing
    const int q2 = lane >> 3;
    const int lr = lane & 7;
    const int aMrow = wm * 32 + (q2 & 1) * 8 + lr;  // + mf*16
    const int aKoff = (q2 >> 1) * 8;                // + q*16
    const int bNrow = wn * 64 + (q2 >> 1) * 8 + lr; // + p*16
    const int bKoff = (q2 & 1) * 8;                 // + q*16

    const uint32_t sA = (uint32_t)__cvta_generic_to_shared(&As[0][0]);
    const uint32_t sB = (uint32_t)__cvta_generic_to_shared(&Bs[0][0]);

    float acc[2][8][4];
#pragma unroll
    for (int i = 0; i < 2; i++)
#pragma unroll
        for (int j = 0; j < 8; j++)
#pragma unroll
            for (int r = 0; r < 4; r++) acc[i][j][r] = 0.0f;

    // ---- prologue: load iter 0 ----
    {
        const __nv_bfloat16* Asrc = Ahi;       // seg 0
        const __nv_bfloat16* Bsrc = Bhi;
        uint4 a0 = *(const uint4*)(Asrc + (size_t)(bm + lrow) * KDIM + lcc * 8);
        uint4 a1 = *(const uint4*)(Asrc + (size_t)(bm + lrow + 64) * KDIM + lcc * 8);
        uint4 b0 = *(const uint4*)(Bsrc + (size_t)(bn + lrow) * KDIM + lcc * 8);
        uint4 b1 = *(const uint4*)(Bsrc + (size_t)(bn + lrow + 64) * KDIM + lcc * 8);
        *(uint4*)&As[0][soff0] = a0;
        *(uint4*)&As[0][soff1] = a1;
        *(uint4*)&Bs[0][soff0] = b0;
        *(uint4*)&Bs[0][soff1] = b1;
    }
    __syncthreads();

    int buf = 0;
    for (int it = 0; it < GITERS; it++) {
        uint4 na0, na1, nb0, nb1;
        const bool has_next = (it + 1 < GITERS);
        if (has_next) {
            const int kk   = (it + 1) * 32;
            const int seg  = kk >> 11;
            const int kloc = kk & (KDIM - 1);
            const __nv_bfloat16* Asrc = (seg < 2) ? Ahi : Alo;
            const __nv_bfloat16* Bsrc = (seg == 1) ? Blo : Bhi;
            na0 = *(const uint4*)(Asrc + (size_t)(bm + lrow) * KDIM + kloc + lcc * 8);
            na1 = *(const uint4*)(Asrc + (size_t)(bm + lrow + 64) * KDIM + kloc + lcc * 8);
            nb0 = *(const uint4*)(Bsrc + (size_t)(bn + lrow) * KDIM + kloc + lcc * 8);
            nb1 = *(const uint4*)(Bsrc + (size_t)(bn + lrow + 64) * KDIM + kloc + lcc * 8);
        }

        const uint32_t sAb = sA + (uint32_t)buf * (128 * GSTR * 2);
        const uint32_t sBb = sB + (uint32_t)buf * (128 * GSTR * 2);
#pragma unroll
        for (int q = 0; q < 2; q++) {
            uint32_t a[2][4];
#pragma unroll
            for (int mf = 0; mf < 2; mf++) {
                uint32_t addr = sAb + (uint32_t)(((aMrow + mf * 16) * GSTR +
                                                  q * 16 + aKoff) * 2);
                ldm_x4(addr, a[mf][0], a[mf][1], a[mf][2], a[mf][3]);
            }
            uint32_t b[4][4];
#pragma unroll
            for (int p = 0; p < 4; p++) {
                uint32_t addr = sBb + (uint32_t)(((bNrow + p * 16) * GSTR +
                                                  q * 16 + bKoff) * 2);
                ldm_x4(addr, b[p][0], b[p][1], b[p][2], b[p][3]);
            }
#pragma unroll
            for (int mf = 0; mf < 2; mf++)
#pragma unroll
                for (int nf = 0; nf < 8; nf++) {
                    uint32_t bb0 = b[nf >> 1][(nf & 1) * 2 + 0];
                    uint32_t bb1 = b[nf >> 1][(nf & 1) * 2 + 1];
                    mma16816(acc[mf][nf], a[mf], bb0, bb1);
                }
        }

        if (has_next) {
            const int nb = buf ^ 1;
            *(uint4*)&As[nb][soff0] = na0;
            *(uint4*)&As[nb][soff1] = na1;
            *(uint4*)&Bs[nb][soff0] = nb0;
            *(uint4*)&Bs[nb][soff1] = nb1;
        }
        __syncthreads();
        buf ^= 1;
    }

    // ---- epilogue ----
    const int mbase = bm + wm * 32 + (lane >> 2);
    const int nbase = bn + wn * 64 + (lane & 3) * 2;
#pragma unroll
    for (int mf = 0; mf < 2; mf++) {
#pragma unroll
        for (int nf = 0; nf < 8; nf++) {
            const int c = nbase + nf * 8;
            const float bi0 = __ldg(bias + c);
            const float bi1 = __ldg(bias + c + 1);
            const int r0 = mbase + mf * 16;
            float2 v0 = make_float2(acc[mf][nf][0] + bi0, acc[mf][nf][1] + bi1);
            float2 v1 = make_float2(acc[mf][nf][2] + bi0, acc[mf][nf][3] + bi1);
            *(float2*)(C + (size_t)r0 * N + c)       = v0;
            *(float2*)(C + (size_t)(r0 + 8) * N + c) = v1;
        }
    }
}

// ---------------------------------------------------------------------------
// Highway combine: h = g*h + (1-g)*relu(t)
// ---------------------------------------------------------------------------
__global__ __launch_bounds__(256)
void highway_kernel(const float* __restrict__ p, float* __restrict__ h) {
    int idx = blockIdx.x * blockDim.x + threadIdx.x;
    int total = NTOK * (NFILT / 4);
    if (idx >= total) return;
    int m  = idx / (NFILT / 4);
    int j4 = idx % (NFILT / 4);

    const float4 pt = *(const float4*)(p + (size_t)m * (2 * NFILT) + j4 * 4);
    const float4 pg = *(const float4*)(p + (size_t)m * (2 * NFILT) + NFILT + j4 * 4);
    float4 hv = *(float4*)(h + (size_t)m * NFILT + j4 * 4);

    float g;
    g = 1.0f / (1.0f + expf(-pg.x)); hv.x = g * hv.x + (1.0f - g) * fmaxf(pt.x, 0.0f);
    g = 1.0f / (1.0f + expf(-pg.y)); hv.y = g * hv.y + (1.0f - g) * fmaxf(pt.y, 0.0f);
    g = 1.0f / (1.0f + expf(-pg.z)); hv.z = g * hv.z + (1.0f - g) * fmaxf(pt.z, 0.0f);
    g = 1.0f / (1.0f + expf(-pg.w)); hv.w = g * hv.w + (1.0f - g) * fmaxf(pt.w, 0.0f);

    *(float4*)(h + (size_t)m * NFILT + j4 * 4) = hv;
}

// ---------------------------------------------------------------------------
// Launch
// ---------------------------------------------------------------------------
extern "C" void kernel_launch(void* const* d_in, const int* in_sizes, int n_in,
                              void* d_out, int out_size) {
    const int*   chars  = (const int*)d_in[1];
    const float* emb    = (const float*)d_in[2];
    const float* cw[7], *cb[7];
    for (int i = 0; i < 7; i++) {
        cw[i] = (const float*)d_in[3 + 2 * i];
        cb[i] = (const float*)d_in[4 + 2 * i];
    }
    const float* hw_w0  = (const float*)d_in[17];
    const float* hw_b0  = (const float*)d_in[18];
    const float* hw_w1  = (const float*)d_in[19];
    const float* hw_b1  = (const float*)d_in[20];
    const float* proj_w = (const float*)d_in[21];
    const float* proj_b = (const float*)d_in[22];
    float* out = (float*)d_out;

    static float* hbuf = nullptr;
    static float* pbuf = nullptr;
    static __nv_bfloat16 *hhi, *hlo, *w0hi, *w0lo, *w1hi, *w1lo, *wphi, *wplo;
    if (!hbuf) {
        cudaGetSymbolAddress((void**)&hbuf, g_h);
        cudaGetSymbolAddress((void**)&pbuf, g_p);
        cudaGetSymbolAddress((void**)&hhi,  g_hhi);
        cudaGetSymbolAddress((void**)&hlo,  g_hlo);
        cudaGetSymbolAddress((void**)&w0hi, g_w0hi);
        cudaGetSymbolAddress((void**)&w0lo, g_w0lo);
        cudaGetSymbolAddress((void**)&w1hi, g_w1hi);
        cudaGetSymbolAddress((void**)&w1lo, g_w1lo);
        cudaGetSymbolAddress((void**)&wphi, g_wphi);
        cudaGetSymbolAddress((void**)&wplo, g_wplo);
    }

    dim3 blk(256);
    const int nH  = NTOK * NFILT;            // 8.4M
    const int nW  = 2 * NFILT * NFILT;       // 8.4M
    const int nWP = PROJ * NFILT;            // 1.05M
    auto cvb = [](int n) { return (n / 4 + 255) / 256; };

    // weight splits (recomputed each call; deterministic & cheap)
    cvt_split<<<cvb(nW),  blk>>>(hw_w0,  w0hi, w0lo, nW / 4);
    cvt_split<<<cvb(nW),  blk>>>(hw_w1,  w1hi, w1lo, nW / 4);
    cvt_split<<<cvb(nWP), blk>>>(proj_w, wphi, wplo, nWP / 4);

    // 1) conv stage
    conv_kernel<<<NTOK, 256>>>(chars, emb,
                               cw[0], cb[0], cw[1], cb[1], cw[2], cb[2],
                               cw[3], cb[3], cw[4], cb[4], cw[5], cb[5],
                               cw[6], cb[6], hbuf);

    dim3 grid_hw(2 * NFILT / 128, NTOK / 128);   // (32, 32)
    dim3 grid_pr(PROJ / 128, NTOK / 128);        // (4, 32)
    int hw_blocks = (NTOK * (NFILT / 4) + 255) / 256;

    // 2-3) highway layer 0
    cvt_split<<<cvb(nH), blk>>>(hbuf, hhi, hlo, nH / 4);
    gemm_bf16x3<<<grid_hw, blk>>>(hhi, hlo, w0hi, w0lo, hw_b0, pbuf, NTOK, 2 * NFILT);
    highway_kernel<<<hw_blocks, blk>>>(pbuf, hbuf);

    // 4-5) highway layer 1
    cvt_split<<<cvb(nH), blk>>>(hbuf, hhi, hlo, nH / 4);
    gemm_bf16x3<<<grid_hw, blk>>>(hhi, hlo, w1hi, w1lo, hw_b1, pbuf, NTOK, 2 * NFILT);
    highway_kernel<<<hw_blocks, blk>>>(pbuf, hbuf);

    // 6) projection
    cvt_split<<<cvb(nH), blk>>>(hbuf, hhi, hlo, nH / 4);
    gemm_bf16x3<<<grid_pr, blk>>>(hhi, hlo, wphi, wplo, proj_b, out, NTOK, PROJ);
}

// round 4
// speedup vs baseline: 1.4680x; 1.4680x over previous
#include <cuda_runtime.h>
#include <cuda_bf16.h>
#include <math.h>
#include <stdint.h>

// ---------------------------------------------------------------------------
// ConvTokenEmbedder: char CNN + highway x2 + projection
// Round 4: mma.sync bf16x3 GEMM w/ 4-stage cp.async; conv w/ transposed
//          (coalesced) weights; h-split fused into conv/highway epilogues.
// ---------------------------------------------------------------------------

#define NTOK   4096
#define NFILT  2048
#define PROJ   512
#define MAXC   50
#define CDIM   16
#define KDIM   2048

// Scratch
__device__ float g_h[NTOK * NFILT];
__device__ float g_p[NTOK * 2 * NFILT];
__device__ float g_wt[197120];                 // transposed conv weights
__device__ __nv_bfloat16 g_hhi[NTOK * NFILT];
__device__ __nv_bfloat16 g_hlo[NTOK * NFILT];
__device__ __nv_bfloat16 g_w0hi[2 * NFILT * NFILT];
__device__ __nv_bfloat16 g_w0lo[2 * NFILT * NFILT];
__device__ __nv_bfloat16 g_w1hi[2 * NFILT * NFILT];
__device__ __nv_bfloat16 g_w1lo[2 * NFILT * NFILT];
__device__ __nv_bfloat16 g_wphi[PROJ * NFILT];
__device__ __nv_bfloat16 g_wplo[PROJ * NFILT];

// transposed weight offsets (floats): per group nf * 16 * W
// w1:512  w2:1024  w3:3072  w4:8192  w5:20480  w6:49152  w7:114688
#define WT_O0 0
#define WT_O1 512
#define WT_O2 1536
#define WT_O3 4608
#define WT_O4 12800
#define WT_O5 33280
#define WT_O6 82432

// ---------------------------------------------------------------------------
// Weight transpose: in[f][r] (r = c*W+k, size cw) -> out[r][f]
// ---------------------------------------------------------------------------
__global__ __launch_bounds__(256)
void transpose_w(const float* __restrict__ in, float* __restrict__ out,
                 int nf, int cw) {
    int idx = blockIdx.x * blockDim.x + threadIdx.x;
    if (idx >= nf * cw) return;
    int f = idx / cw;
    int r = idx % cw;
    out[r * nf + f] = in[idx];
}

// ---------------------------------------------------------------------------
// Conv stage — coalesced transposed weights: wt[(c*W+k)*nf + f]
// ---------------------------------------------------------------------------
template <int W>
__device__ __forceinline__ float conv_max_t(const float* __restrict__ xs,
                                            const float* __restrict__ wt,
                                            int nf, int f, float bias) {
    constexpr int NT = 51 - W;
    constexpr int TC = (NT + 1) / 2;
    float best = -3.4e38f;
#pragma unroll
    for (int ch = 0; ch < 2; ch++) {
        const int t0 = (ch == 0) ? 0 : (NT - TC);
        float acc[TC];
#pragma unroll
        for (int t = 0; t < TC; t++) acc[t] = 0.0f;
#pragma unroll 2
        for (int c = 0; c < CDIM; c++) {
            float wr[W];
#pragma unroll
            for (int k = 0; k < W; k++) wr[k] = wt[(c * W + k) * nf + f];
#pragma unroll
            for (int j = 0; j < TC + W - 1; j++) {
                float xv = xs[c * 51 + t0 + j];
#pragma unroll
                for (int k = 0; k < W; k++) {
                    int t = j - k;
                    if (t >= 0 && t < TC) acc[t] = fmaf(xv, wr[k], acc[t]);
                }
            }
        }
#pragma unroll
        for (int t = 0; t < TC; t++) best = fmaxf(best, acc[t]);
    }
    best += bias;
    return fmaxf(best, 0.0f);
}

__device__ __forceinline__ void store_split(float r, float* h,
                                            __nv_bfloat16* hi,
                                            __nv_bfloat16* lo, size_t o) {
    h[o] = r;
    __nv_bfloat16 hh = __float2bfloat16(r);
    hi[o] = hh;
    lo[o] = __float2bfloat16(r - __bfloat162float(hh));
}

__global__ __launch_bounds__(256)
void conv_kernel(const int*   __restrict__ chars,
                 const float* __restrict__ emb,
                 const float* __restrict__ wt,
                 const float* __restrict__ b0, const float* __restrict__ b1,
                 const float* __restrict__ b2, const float* __restrict__ b3,
                 const float* __restrict__ b4, const float* __restrict__ b5,
                 const float* __restrict__ b6,
                 float* __restrict__ h,
                 __nv_bfloat16* __restrict__ hhi,
                 __nv_bfloat16* __restrict__ hlo) {
    __shared__ float xs[CDIM * 51];
    __shared__ int   chs[MAXC];

    const int n   = blockIdx.x;
    const int tid = threadIdx.x;

    if (tid < MAXC) chs[tid] = chars[n * MAXC + tid];
    __syncthreads();
    for (int idx = tid; idx < MAXC * CDIM; idx += 256) {
        int t = idx >> 4;
        int c = idx & 15;
        xs[c * 51 + t] = emb[chs[t] * CDIM + c];
    }
    __syncthreads();

    const size_t rowo = (size_t)n * NFILT;
    {
        int f = tid;
        float r;
        if (f < 32)        r = conv_max_t<1>(xs, wt + WT_O0, 32,  f,       b0[f]);
        else if (f < 64)   r = conv_max_t<2>(xs, wt + WT_O1, 32,  f - 32,  b1[f - 32]);
        else if (f < 128)  r = conv_max_t<3>(xs, wt + WT_O2, 64,  f - 64,  b2[f - 64]);
        else               r = conv_max_t<4>(xs, wt + WT_O3, 128, f - 128, b3[f - 128]);
        store_split(r, h, hhi, hlo, rowo + f);
    }
    {
        int f = tid;
        float r = conv_max_t<5>(xs, wt + WT_O4, 256, f, b4[f]);
        store_split(r, h, hhi, hlo, rowo + 256 + f);
    }
#pragma unroll
    for (int i = 0; i < 2; i++) {
        int f = tid + i * 256;
        float r = conv_max_t<6>(xs, wt + WT_O5, 512, f, b5[f]);
        store_split(r, h, hhi, hlo, rowo + 512 + f);
    }
#pragma unroll
    for (int i = 0; i < 4; i++) {
        int f = tid + i * 256;
        float r = conv_max_t<7>(xs, wt + WT_O6, 1024, f, b6[f]);
        store_split(r, h, hhi, hlo, rowo + 1024 + f);
    }
}

// ---------------------------------------------------------------------------
// fp32 -> (bf16 hi, bf16 lo) split (weights only)
// ---------------------------------------------------------------------------
__global__ __launch_bounds__(256)
void cvt_split(const float* __restrict__ x,
               __nv_bfloat16* __restrict__ hi,
               __nv_bfloat16* __restrict__ lo, int n4) {
    int i = blockIdx.x * blockDim.x + threadIdx.x;
    if (i >= n4) return;
    float4 v = ((const float4*)x)[i];
    __nv_bfloat16 h0 = __float2bfloat16(v.x);
    __nv_bfloat16 h1 = __float2bfloat16(v.y);
    __nv_bfloat16 h2 = __float2bfloat16(v.z);
    __nv_bfloat16 h3 = __float2bfloat16(v.w);
    __nv_bfloat16 l0 = __float2bfloat16(v.x - __bfloat162float(h0));
    __nv_bfloat16 l1 = __float2bfloat16(v.y - __bfloat162float(h1));
    __nv_bfloat16 l2 = __float2bfloat16(v.z - __bfloat162float(h2));
    __nv_bfloat16 l3 = __float2bfloat16(v.w - __bfloat162float(h3));
    __nv_bfloat162* hp = (__nv_bfloat162*)hi;
    __nv_bfloat162* lp = (__nv_bfloat162*)lo;
    hp[i * 2 + 0] = __halves2bfloat162(h0, h1);
    hp[i * 2 + 1] = __halves2bfloat162(h2, h3);
    lp[i * 2 + 0] = __halves2bfloat162(l0, l1);
    lp[i * 2 + 1] = __halves2bfloat162(l2, l3);
}

// ---------------------------------------------------------------------------
// bf16x3 tensor GEMM (TN), 4-stage cp.async pipeline
//   K' = 3*2048 = 6144 fused (hi*hi, hi*lo, lo*hi); BK=32; tile 128x128
//   warps 4(m) x 2(n), warp tile 32x64; mma.sync.m16n8k16 bf16, fp32 accum
// ---------------------------------------------------------------------------
#define GSTR   40                    // smem row stride (bf16 elems)
#define NSTAGE 4
#define STAGEB (128 * GSTR * 2)      // bytes per matrix per stage (10240)
#define GITERS 192                   // 6144 / 32

__device__ __forceinline__ void ldm_x4(uint32_t addr, uint32_t& r0, uint32_t& r1,
                                       uint32_t& r2, uint32_t& r3) {
    asm volatile("ldmatrix.sync.aligned.m8n8.x4.shared.b16 {%0,%1,%2,%3}, [%4];"
                 : "=r"(r0), "=r"(r1), "=r"(r2), "=r"(r3) : "r"(addr));
}

__device__ __forceinline__ void mma16816(float* c, const uint32_t* a,
                                         uint32_t b0, uint32_t b1) {
    asm volatile(
        "mma.sync.aligned.m16n8k16.row.col.f32.bf16.bf16.f32 "
        "{%0,%1,%2,%3}, {%4,%5,%6,%7}, {%8,%9}, {%0,%1,%2,%3};"
        : "+f"(c[0]), "+f"(c[1]), "+f"(c[2]), "+f"(c[3])
        : "r"(a[0]), "r"(a[1]), "r"(a[2]), "r"(a[3]), "r"(b0), "r"(b1));
}

__device__ __forceinline__ void cp16(uint32_t s, const void* g) {
    asm volatile("cp.async.cg.shared.global [%0], [%1], 16;" :: "r"(s), "l"(g));
}
#define CP_COMMIT() asm volatile("cp.async.commit_group;" ::: "memory")
#define CP_WAIT(n)  asm volatile("cp.async.wait_group %0;" :: "n"(n) : "memory")

__device__ __forceinline__ uint32_t smem_u32(const void* p) {
    uint32_t a;
    asm("{ .reg .u64 t; cvta.to.shared.u64 t, %1; cvt.u32.u64 %0, t; }"
        : "=r"(a) : "l"(p));
    return a;
}

__global__ __launch_bounds__(256, 2)
void gemm_bf16x3(const __nv_bfloat16* __restrict__ Ahi,
                 const __nv_bfloat16* __restrict__ Alo,
                 const __nv_bfloat16* __restrict__ Bhi,
                 const __nv_bfloat16* __restrict__ Blo,
                 const float* __restrict__ bias,
                 float* __restrict__ C, int Ntot) {
    extern __shared__ __nv_bfloat16 sm[];
    const uint32_t sbase = smem_u32(sm);

    const int tid  = threadIdx.x;
    const int lane = tid & 31;
    const int warp = tid >> 5;
    const int wm   = warp & 3;
    const int wn   = warp >> 2;
    const int bm   = blockIdx.y * 128;
    const int bn   = blockIdx.x * 128;

    // cp.async mapping: row = tid>>1 (0..127), chunks {(tid&1)*2, +1} of 16B
    const int lrow = tid >> 1;
    const int lc0  = (tid & 1) * 2;

    // ldmatrix lane addressing (verified round 2)
    const int q2 = lane >> 3;
    const int lr = lane & 7;
    const int aMrow = wm * 32 + (q2 & 1) * 8 + lr;
    const int aKoff = (q2 >> 1) * 8;
    const int bNrow = wn * 64 + (q2 >> 1) * 8 + lr;
    const int bKoff = (q2 & 1) * 8;

    float acc[2][8][4];
#pragma unroll
    for (int i = 0; i < 2; i++)
#pragma unroll
        for (int j = 0; j < 8; j++)
#pragma unroll
            for (int r = 0; r < 4; r++) acc[i][j][r] = 0.0f;

    // issue loads for logical iter `kk` into stage slot `s`
    auto issue = [&](int it, int s) {
        const int seg  = it >> 6;
        const int kloc = (it & 63) * 32;
        const __nv_bfloat16* Asrc = (seg < 2) ? Ahi : Alo;
        const __nv_bfloat16* Bsrc = (seg == 1) ? Blo : Bhi;
        const uint32_t ab = sbase + (uint32_t)s * (2 * STAGEB);
        const uint32_t bb = ab + STAGEB;
#pragma unroll
        for (int j = 0; j < 2; j++) {
            const int c = lc0 + j;
            cp16(ab + (uint32_t)(lrow * GSTR + c * 8) * 2,
                 Asrc + (size_t)(bm + lrow) * KDIM + kloc + c * 8);
            cp16(bb + (uint32_t)(lrow * GSTR + c * 8) * 2,
                 Bsrc + (size_t)(bn + lrow) * KDIM + kloc + c * 8);
        }
    };

    // prologue: fill stages 0..NSTAGE-2
#pragma unroll
    for (int s = 0; s < NSTAGE - 1; s++) {
        issue(s, s);
        CP_COMMIT();
    }

    for (int it = 0; it < GITERS; it++) {
        CP_WAIT(NSTAGE - 2);          // stage `it` complete
        __syncthreads();

        // prefetch stage it+NSTAGE-1 (overwrites slot consumed at it-1)
        if (it + NSTAGE - 1 < GITERS) issue(it + NSTAGE - 1, (it + NSTAGE - 1) % NSTAGE);
        CP_COMMIT();

        const int s = it % NSTAGE;
        const uint32_t sAb = sbase + (uint32_t)s * (2 * STAGEB);
        const uint32_t sBb = sAb + STAGEB;
#pragma unroll
        for (int q = 0; q < 2; q++) {
            uint32_t a[2][4];
#pragma unroll
            for (int mf = 0; mf < 2; mf++)
                ldm_x4(sAb + (uint32_t)(((aMrow + mf * 16) * GSTR + q * 16 + aKoff) * 2),
                       a[mf][0], a[mf][1], a[mf][2], a[mf][3]);
            uint32_t b[4][4];
#pragma unroll
            for (int p = 0; p < 4; p++)
                ldm_x4(sBb + (uint32_t)(((bNrow + p * 16) * GSTR + q * 16 + bKoff) * 2),
                       b[p][0], b[p][1], b[p][2], b[p][3]);
#pragma unroll
            for (int mf = 0; mf < 2; mf++)
#pragma unroll
                for (int nf = 0; nf < 8; nf++)
                    mma16816(acc[mf][nf], a[mf],
                             b[nf >> 1][(nf & 1) * 2 + 0],
                             b[nf >> 1][(nf & 1) * 2 + 1]);
        }
    }

    // epilogue
    const int mbase = bm + wm * 32 + (lane >> 2);
    const int nbase = bn + wn * 64 + (lane & 3) * 2;
#pragma unroll
    for (int mf = 0; mf < 2; mf++) {
#pragma unroll
        for (int nf = 0; nf < 8; nf++) {
            const int c = nbase + nf * 8;
            const float bi0 = __ldg(bias + c);
            const float bi1 = __ldg(bias + c + 1);
            const int r0 = mbase + mf * 16;
            *(float2*)(C + (size_t)r0 * Ntot + c) =
                make_float2(acc[mf][nf][0] + bi0, acc[mf][nf][1] + bi1);
            *(float2*)(C + (size_t)(r0 + 8) * Ntot + c) =
                make_float2(acc[mf][nf][2] + bi0, acc[mf][nf][3] + bi1);
        }
    }
}

// ---------------------------------------------------------------------------
// Highway combine: h = g*h + (1-g)*relu(t)  + fused bf16 hi/lo split of new h
// ---------------------------------------------------------------------------
__global__ __launch_bounds__(256)
void highway_kernel(const float* __restrict__ p, float* __restrict__ h,
                    __nv_bfloat16* __restrict__ hhi,
                    __nv_bfloat16* __restrict__ hlo) {
    int idx = blockIdx.x * blockDim.x + threadIdx.x;
    int total = NTOK * (NFILT / 4);
    if (idx >= total) return;
    int m  = idx / (NFILT / 4);
    int j4 = idx % (NFILT / 4);

    const float4 pt = *(const float4*)(p + (size_t)m * (2 * NFILT) + j4 * 4);
    const float4 pg = *(const float4*)(p + (size_t)m * (2 * NFILT) + NFILT + j4 * 4);
    float4 hv = *(float4*)(h + (size_t)m * NFILT + j4 * 4);

    float g;
    g = 1.0f / (1.0f + expf(-pg.x)); hv.x = g * hv.x + (1.0f - g) * fmaxf(pt.x, 0.0f);
    g = 1.0f / (1.0f + expf(-pg.y)); hv.y = g * hv.y + (1.0f - g) * fmaxf(pt.y, 0.0f);
    g = 1.0f / (1.0f + expf(-pg.z)); hv.z = g * hv.z + (1.0f - g) * fmaxf(pt.z, 0.0f);
    g = 1.0f / (1.0f + expf(-pg.w)); hv.w = g * hv.w + (1.0f - g) * fmaxf(pt.w, 0.0f);

    *(float4*)(h + (size_t)m * NFILT + j4 * 4) = hv;

    __nv_bfloat16 h0 = __float2bfloat16(hv.x);
    __nv_bfloat16 h1 = __float2bfloat16(hv.y);
    __nv_bfloat16 h2 = __float2bfloat16(hv.z);
    __nv_bfloat16 h3 = __float2bfloat16(hv.w);
    __nv_bfloat162* hp = (__nv_bfloat162*)(hhi + (size_t)m * NFILT + j4 * 4);
    __nv_bfloat162* lp = (__nv_bfloat162*)(hlo + (size_t)m * NFILT + j4 * 4);
    hp[0] = __halves2bfloat162(h0, h1);
    hp[1] = __halves2bfloat162(h2, h3);
    lp[0] = __halves2bfloat162(__float2bfloat16(hv.x - __bfloat162float(h0)),
                               __float2bfloat16(hv.y - __bfloat162float(h1)));
    lp[1] = __halves2bfloat162(__float2bfloat16(hv.z - __bfloat162float(h2)),
                               __float2bfloat16(hv.w - __bfloat162float(h3)));
}

// ---------------------------------------------------------------------------
// Launch
// ---------------------------------------------------------------------------
#define GEMM_DSMEM (NSTAGE * 2 * STAGEB)   // 81920

extern "C" void kernel_launch(void* const* d_in, const int* in_sizes, int n_in,
                              void* d_out, int out_size) {
    const int*   chars  = (const int*)d_in[1];
    const float* emb    = (const float*)d_in[2];
    const float* cw[7], *cb[7];
    for (int i = 0; i < 7; i++) {
        cw[i] = (const float*)d_in[3 + 2 * i];
        cb[i] = (const float*)d_in[4 + 2 * i];
    }
    const float* hw_w0  = (const float*)d_in[17];
    const float* hw_b0  = (const float*)d_in[18];
    const float* hw_w1  = (const float*)d_in[19];
    const float* hw_b1  = (const float*)d_in[20];
    const float* proj_w = (const float*)d_in[21];
    const float* proj_b = (const float*)d_in[22];
    float* out = (float*)d_out;

    static float *hbuf = nullptr, *pbuf = nullptr, *wtbuf = nullptr;
    static __nv_bfloat16 *hhi, *hlo, *w0hi, *w0lo, *w1hi, *w1lo, *wphi, *wplo;
    if (!hbuf) {
        cudaGetSymbolAddress((void**)&hbuf,  g_h);
        cudaGetSymbolAddress((void**)&pbuf,  g_p);
        cudaGetSymbolAddress((void**)&wtbuf, g_wt);
        cudaGetSymbolAddress((void**)&hhi,   g_hhi);
        cudaGetSymbolAddress((void**)&hlo,   g_hlo);
        cudaGetSymbolAddress((void**)&w0hi,  g_w0hi);
        cudaGetSymbolAddress((void**)&w0lo,  g_w0lo);
        cudaGetSymbolAddress((void**)&w1hi,  g_w1hi);
        cudaGetSymbolAddress((void**)&w1lo,  g_w1lo);
        cudaGetSymbolAddress((void**)&wphi,  g_wphi);
        cudaGetSymbolAddress((void**)&wplo,  g_wplo);
        cudaFuncSetAttribute(gemm_bf16x3,
                             cudaFuncAttributeMaxDynamicSharedMemorySize,
                             GEMM_DSMEM);
    }

    dim3 blk(256);
    const int nW  = 2 * NFILT * NFILT;
    const int nWP = PROJ * NFILT;
    auto cvb = [](int n) { return (n / 4 + 255) / 256; };

    // conv weight transposes (tiny)
    const int wt_off[7] = {WT_O0, WT_O1, WT_O2, WT_O3, WT_O4, WT_O5, WT_O6};
    const int wt_nf[7]  = {32, 32, 64, 128, 256, 512, 1024};
    for (int i = 0; i < 7; i++) {
        int cw_i = CDIM * (i + 1);
        int tot  = wt_nf[i] * cw_i;
        transpose_w<<<(tot + 255) / 256, blk>>>(cw[i], wtbuf + wt_off[i],
                                                wt_nf[i], cw_i);
    }

    // GEMM weight splits
    cvt_split<<<cvb(nW),  blk>>>(hw_w0,  w0hi, w0lo, nW / 4);
    cvt_split<<<cvb(nW),  blk>>>(hw_w1,  w1hi, w1lo, nW / 4);
    cvt_split<<<cvb(nWP), blk>>>(proj_w, wphi, wplo, nWP / 4);

    // 1) conv stage (writes h + hi/lo split)
    conv_kernel<<<NTOK, 256>>>(chars, emb, wtbuf,
                               cb[0], cb[1], cb[2], cb[3], cb[4], cb[5], cb[6],
                               hbuf, hhi, hlo);

    dim3 grid_hw(2 * NFILT / 128, NTOK / 128);   // (32, 32)
    dim3 grid_pr(PROJ / 128, NTOK / 128);        // (4, 32)
    int hw_blocks = (NTOK * (NFILT / 4) + 255) / 256;

    // 2-3) highway layer 0
    gemm_bf16x3<<<grid_hw, blk, GEMM_DSMEM>>>(hhi, hlo, w0hi, w0lo, hw_b0,
                                              pbuf, 2 * NFILT);
    highway_kernel<<<hw_blocks, blk>>>(pbuf, hbuf, hhi, hlo);

    // 4-5) highway layer 1
    gemm_bf16x3<<<grid_hw, blk, GEMM_DSMEM>>>(hhi, hlo, w1hi, w1lo, hw_b1,
                                              pbuf, 2 * NFILT);
    highway_kernel<<<hw_blocks, blk>>>(pbuf, hbuf, hhi, hlo);

    // 6) projection
    gemm_bf16x3<<<grid_pr, blk, GEMM_DSMEM>>>(hhi, hlo, wphi, wplo, proj_b,
                                              out, PROJ);
}

// round 5
// speedup vs baseline: 1.9903x; 1.3557x over previous
#include <cuda_runtime.h>
#include <cuda_bf16.h>
#include <math.h>
#include <stdint.h>

// ---------------------------------------------------------------------------
// ConvTokenEmbedder: char CNN + highway x2 + projection
// Round 5: conv via packed fma.rn.f32x2 (2 fp32 FMA / issue);
//          highway GEMMs on 128x256 tile (64x64 warp tile, 4-stage cp.async)
// ---------------------------------------------------------------------------

#define NTOK   4096
#define NFILT  2048
#define PROJ   512
#define MAXC   50
#define CDIM   16
#define KDIM   2048

typedef unsigned long long u64;

// Scratch
__device__ float g_h[NTOK * NFILT];
__device__ float g_p[NTOK * 2 * NFILT];
__device__ float g_wt[197120];                 // transposed conv weights
__device__ __nv_bfloat16 g_hhi[NTOK * NFILT];
__device__ __nv_bfloat16 g_hlo[NTOK * NFILT];
__device__ __nv_bfloat16 g_w0hi[2 * NFILT * NFILT];
__device__ __nv_bfloat16 g_w0lo[2 * NFILT * NFILT];
__device__ __nv_bfloat16 g_w1hi[2 * NFILT * NFILT];
__device__ __nv_bfloat16 g_w1lo[2 * NFILT * NFILT];
__device__ __nv_bfloat16 g_wphi[PROJ * NFILT];
__device__ __nv_bfloat16 g_wplo[PROJ * NFILT];

#define WT_O0 0
#define WT_O1 512
#define WT_O2 1536
#define WT_O3 4608
#define WT_O4 12800
#define WT_O5 33280
#define WT_O6 82432

// ---------------------------------------------------------------------------
// packed f32x2 helpers
// ---------------------------------------------------------------------------
__device__ __forceinline__ u64 fma_x2(u64 a, u64 b, u64 c) {
    u64 d;
    asm("fma.rn.f32x2 %0, %1, %2, %3;" : "=l"(d) : "l"(a), "l"(b), "l"(c));
    return d;
}
__device__ __forceinline__ u64 pack2(float lo, float hi) {
    u64 d;
    asm("mov.b64 %0, {%1, %2};" : "=l"(d) : "f"(lo), "f"(hi));
    return d;
}
__device__ __forceinline__ float2 unpack2(u64 v) {
    float lo, hi;
    asm("mov.b64 {%0, %1}, %2;" : "=f"(lo), "=f"(hi) : "l"(v));
    return make_float2(lo, hi);
}

// ---------------------------------------------------------------------------
// Weight transpose: in[f][r] (r = c*W+k) -> out[r][f]
// ---------------------------------------------------------------------------
__global__ __launch_bounds__(256)
void transpose_w(const float* __restrict__ in, float* __restrict__ out,
                 int nf, int cw) {
    int idx = blockIdx.x * blockDim.x + threadIdx.x;
    if (idx >= nf * cw) return;
    int f = idx / cw;
    int r = idx % cw;
    out[r * nf + f] = in[idx];
}

// ---------------------------------------------------------------------------
// Conv stage — packed two-chunk accumulation via fma.rn.f32x2
//   xs2_W[c][j] = (xs[c][j], xs[c][OFF+j]);  acc2[t] = (acc_c0[t], acc_c1[t])
// ---------------------------------------------------------------------------
// per-width constants: NT=51-W, TC=(NT+1)/2, OFF=NT-TC, J=TC+W-1
// W:   1   2   3   4   5   6   7
// TC: 25  25  24  24  23  23  22
// OFF:25  24  24  23  23  22  22
// J:  25  26  26  27  27  28  28
#define XS2_O1 0
#define XS2_O2 400
#define XS2_O3 816
#define XS2_O4 1232
#define XS2_O5 1664
#define XS2_O6 2096
#define XS2_O7 2544
#define XS2_TOT 2992

template <int W>
__device__ __forceinline__ float conv_max2(const u64* __restrict__ xs2,
                                           const float* __restrict__ wt,
                                           int nf, int f, float bias) {
    constexpr int NT = 51 - W;
    constexpr int TC = (NT + 1) / 2;
    constexpr int J  = TC + W - 1;
    u64 acc[TC];
#pragma unroll
    for (int t = 0; t < TC; t++) acc[t] = 0ULL;    // (0.0f, 0.0f)

#pragma unroll 2
    for (int c = 0; c < CDIM; c++) {
        u64 w2[W];
#pragma unroll
        for (int k = 0; k < W; k++) {
            float w = wt[(c * W + k) * nf + f];
            w2[k] = pack2(w, w);
        }
#pragma unroll
        for (int j = 0; j < J; j++) {
            u64 xv = xs2[c * J + j];
#pragma unroll
            for (int k = 0; k < W; k++) {
                int t = j - k;                     // compile-time after unroll
                if (t >= 0 && t < TC) acc[t] = fma_x2(xv, w2[k], acc[t]);
            }
        }
    }
    float best = -3.4e38f;
#pragma unroll
    for (int t = 0; t < TC; t++) {
        float2 v = unpack2(acc[t]);
        best = fmaxf(best, fmaxf(v.x, v.y));
    }
    return fmaxf(best + bias, 0.0f);
}

__device__ __forceinline__ void store_split(float r, float* h,
                                            __nv_bfloat16* hi,
                                            __nv_bfloat16* lo, size_t o) {
    h[o] = r;
    __nv_bfloat16 hh = __float2bfloat16(r);
    hi[o] = hh;
    lo[o] = __float2bfloat16(r - __bfloat162float(hh));
}

__global__ __launch_bounds__(256)
void conv_kernel(const int*   __restrict__ chars,
                 const float* __restrict__ emb,
                 const float* __restrict__ wt,
                 const float* __restrict__ b0, const float* __restrict__ b1,
                 const float* __restrict__ b2, const float* __restrict__ b3,
                 const float* __restrict__ b4, const float* __restrict__ b5,
                 const float* __restrict__ b6,
                 float* __restrict__ h,
                 __nv_bfloat16* __restrict__ hhi,
                 __nv_bfloat16* __restrict__ hlo) {
    __shared__ float xs[CDIM * 51];
    __shared__ int   chs[MAXC];
    __shared__ u64   xs2[XS2_TOT];

    const int n   = blockIdx.x;
    const int tid = threadIdx.x;

    if (tid < MAXC) chs[tid] = chars[n * MAXC + tid];
    __syncthreads();
    for (int idx = tid; idx < MAXC * CDIM; idx += 256) {
        int t = idx >> 4;
        int c = idx & 15;
        xs[c * 51 + t] = emb[chs[t] * CDIM + c];
    }
    __syncthreads();

    // build packed two-chunk x arrays for each width
    {
        const int offs[7] = {XS2_O1, XS2_O2, XS2_O3, XS2_O4, XS2_O5, XS2_O6, XS2_O7};
        const int Js[7]   = {25, 26, 26, 27, 27, 28, 28};
        const int OFFs[7] = {25, 24, 24, 23, 23, 22, 22};
#pragma unroll
        for (int w = 0; w < 7; w++) {
            const int J = Js[w], OFF = OFFs[w];
            u64* dst = xs2 + offs[w];
            for (int idx = tid; idx < CDIM * J; idx += 256) {
                int c = idx / J;
                int j = idx - c * J;
                dst[idx] = pack2(xs[c * 51 + j], xs[c * 51 + OFF + j]);
            }
        }
    }
    __syncthreads();

    const size_t rowo = (size_t)n * NFILT;
    {
        int f = tid;
        float r;
        if (f < 32)        r = conv_max2<1>(xs2 + XS2_O1, wt + WT_O0, 32,  f,       b0[f]);
        else if (f < 64)   r = conv_max2<2>(xs2 + XS2_O2, wt + WT_O1, 32,  f - 32,  b1[f - 32]);
        else if (f < 128)  r = conv_max2<3>(xs2 + XS2_O3, wt + WT_O2, 64,  f - 64,  b2[f - 64]);
        else               r = conv_max2<4>(xs2 + XS2_O4, wt + WT_O3, 128, f - 128, b3[f - 128]);
        store_split(r, h, hhi, hlo, rowo + f);
    }
    {
        int f = tid;
        float r = conv_max2<5>(xs2 + XS2_O5, wt + WT_O4, 256, f, b4[f]);
        store_split(r, h, hhi, hlo, rowo + 256 + f);
    }
#pragma unroll
    for (int i = 0; i < 2; i++) {
        int f = tid + i * 256;
        float r = conv_max2<6>(xs2 + XS2_O6, wt + WT_O5, 512, f, b5[f]);
        store_split(r, h, hhi, hlo, rowo + 512 + f);
    }
#pragma unroll
    for (int i = 0; i < 4; i++) {
        int f = tid + i * 256;
        float r = conv_max2<7>(xs2 + XS2_O7, wt + WT_O6, 1024, f, b6[f]);
        store_split(r, h, hhi, hlo, rowo + 1024 + f);
    }
}

// ---------------------------------------------------------------------------
// fp32 -> (bf16 hi, bf16 lo) split (weights only)
// ---------------------------------------------------------------------------
__global__ __launch_bounds__(256)
void cvt_split(const float* __restrict__ x,
               __nv_bfloat16* __restrict__ hi,
               __nv_bfloat16* __restrict__ lo, int n4) {
    int i = blockIdx.x * blockDim.x + threadIdx.x;
    if (i >= n4) return;
    float4 v = ((const float4*)x)[i];
    __nv_bfloat16 h0 = __float2bfloat16(v.x);
    __nv_bfloat16 h1 = __float2bfloat16(v.y);
    __nv_bfloat16 h2 = __float2bfloat16(v.z);
    __nv_bfloat16 h3 = __float2bfloat16(v.w);
    __nv_bfloat16 l0 = __float2bfloat16(v.x - __bfloat162float(h0));
    __nv_bfloat16 l1 = __float2bfloat16(v.y - __bfloat162float(h1));
    __nv_bfloat16 l2 = __float2bfloat16(v.z - __bfloat162float(h2));
    __nv_bfloat16 l3 = __float2bfloat16(v.w - __bfloat162float(h3));
    __nv_bfloat162* hp = (__nv_bfloat162*)hi;
    __nv_bfloat162* lp = (__nv_bfloat162*)lo;
    hp[i * 2 + 0] = __halves2bfloat162(h0, h1);
    hp[i * 2 + 1] = __halves2bfloat162(h2, h3);
    lp[i * 2 + 0] = __halves2bfloat162(l0, l1);
    lp[i * 2 + 1] = __halves2bfloat162(l2, l3);
}

// ---------------------------------------------------------------------------
// common mma helpers
// ---------------------------------------------------------------------------
#define GSTR   40
#define NSTAGE 4
#define GITERS 192                   // 6144 / 32

__device__ __forceinline__ void ldm_x4(uint32_t addr, uint32_t& r0, uint32_t& r1,
                                       uint32_t& r2, uint32_t& r3) {
    asm volatile("ldmatrix.sync.aligned.m8n8.x4.shared.b16 {%0,%1,%2,%3}, [%4];"
                 : "=r"(r0), "=r"(r1), "=r"(r2), "=r"(r3) : "r"(addr));
}
__device__ __forceinline__ void mma16816(float* c, const uint32_t* a,
                                         uint32_t b0, uint32_t b1) {
    asm volatile(
        "mma.sync.aligned.m16n8k16.row.col.f32.bf16.bf16.f32 "
        "{%0,%1,%2,%3}, {%4,%5,%6,%7}, {%8,%9}, {%0,%1,%2,%3};"
        : "+f"(c[0]), "+f"(c[1]), "+f"(c[2]), "+f"(c[3])
        : "r"(a[0]), "r"(a[1]), "r"(a[2]), "r"(a[3]), "r"(b0), "r"(b1));
}
__device__ __forceinline__ void cp16(uint32_t s, const void* g) {
    asm volatile("cp.async.cg.shared.global [%0], [%1], 16;" :: "r"(s), "l"(g));
}
#define CP_COMMIT() asm volatile("cp.async.commit_group;" ::: "memory")
#define CP_WAIT(n)  asm volatile("cp.async.wait_group %0;" :: "n"(n) : "memory")

__device__ __forceinline__ uint32_t smem_u32(const void* p) {
    uint32_t a;
    asm("{ .reg .u64 t; cvta.to.shared.u64 t, %1; cvt.u32.u64 %0, t; }"
        : "=r"(a) : "l"(p));
    return a;
}

// ---------------------------------------------------------------------------
// bf16x3 GEMM, CTA 128x256, warp tile 64x64 (highway layers)
//   stage: A 10240 B + B 20480 B; 4 stages = 122880 B dynamic smem
// ---------------------------------------------------------------------------
#define BIG_ASTG 10240
#define BIG_BSTG 20480
#define BIG_DSMEM (NSTAGE * (BIG_ASTG + BIG_BSTG))

__global__ __launch_bounds__(256)
void gemm_big(const __nv_bfloat16* __restrict__ Ahi,
              const __nv_bfloat16* __restrict__ Alo,
              const __nv_bfloat16* __restrict__ Bhi,
              const __nv_bfloat16* __restrict__ Blo,
              const float* __restrict__ bias,
              float* __restrict__ C, int Ntot) {
    extern __shared__ __nv_bfloat16 sm[];
    const uint32_t sbase = smem_u32(sm);

    const int tid  = threadIdx.x;
    const int lane = tid & 31;
    const int warp = tid >> 5;
    const int wm   = warp & 1;        // 2 m-warps
    const int wn   = warp >> 1;       // 4 n-warps
    const int bm   = blockIdx.y * 128;
    const int bn   = blockIdx.x * 256;

    const int q2 = lane >> 3;
    const int lr = lane & 7;
    const int aMrow = wm * 64 + (q2 & 1) * 8 + lr;
    const int aKoff = (q2 >> 1) * 8;
    const int bNrow = wn * 64 + (q2 >> 1) * 8 + lr;
    const int bKoff = (q2 & 1) * 8;

    float acc[4][8][4];
#pragma unroll
    for (int i = 0; i < 4; i++)
#pragma unroll
        for (int j = 0; j < 8; j++)
#pragma unroll
            for (int r = 0; r < 4; r++) acc[i][j][r] = 0.0f;

    auto issue = [&](int it, int s) {
        const int seg  = it >> 6;
        const int kloc = (it & 63) * 32;
        const __nv_bfloat16* Asrc = (seg < 2) ? Ahi : Alo;
        const __nv_bfloat16* Bsrc = (seg == 1) ? Blo : Bhi;
        const uint32_t ab = sbase + (uint32_t)s * BIG_ASTG;
        const uint32_t bb = sbase + NSTAGE * BIG_ASTG + (uint32_t)s * BIG_BSTG;
#pragma unroll
        for (int j = 0; j < 2; j++) {                 // A: 2 x 16B
            const int idx = tid * 2 + j;
            const int r = idx >> 2, c = idx & 3;
            cp16(ab + (uint32_t)(r * GSTR + c * 8) * 2,
                 Asrc + (size_t)(bm + r) * KDIM + kloc + c * 8);
        }
#pragma unroll
        for (int j = 0; j < 4; j++) {                 // B: 4 x 16B (row = tid)
            cp16(bb + (uint32_t)(tid * GSTR + j * 8) * 2,
                 Bsrc + (size_t)(bn + tid) * KDIM + kloc + j * 8);
        }
    };

#pragma unroll
    for (int s = 0; s < NSTAGE - 1; s++) {
        issue(s, s);
        CP_COMMIT();
    }

    for (int it = 0; it < GITERS; it++) {
        CP_WAIT(NSTAGE - 2);
        __syncthreads();
        if (it + NSTAGE - 1 < GITERS) issue(it + NSTAGE - 1, (it + NSTAGE - 1) % NSTAGE);
        CP_COMMIT();

        const int s = it % NSTAGE;
        const uint32_t sAb = sbase + (uint32_t)s * BIG_ASTG;
        const uint32_t sBb = sbase + NSTAGE * BIG_ASTG + (uint32_t)s * BIG_BSTG;
#pragma unroll
        for (int q = 0; q < 2; q++) {
            uint32_t a[4][4];
#pragma unroll
            for (int mf = 0; mf < 4; mf++)
                ldm_x4(sAb + (uint32_t)(((aMrow + mf * 16) * GSTR + q * 16 + aKoff) * 2),
                       a[mf][0], a[mf][1], a[mf][2], a[mf][3]);
            uint32_t b[4][4];
#pragma unroll
            for (int p = 0; p < 4; p++)
                ldm_x4(sBb + (uint32_t)(((bNrow + p * 16) * GSTR + q * 16 + bKoff) * 2),
                       b[p][0], b[p][1], b[p][2], b[p][3]);
#pragma unroll
            for (int mf = 0; mf < 4; mf++)
#pragma unroll
                for (int nf = 0; nf < 8; nf++)
                    mma16816(acc[mf][nf], a[mf],
                             b[nf >> 1][(nf & 1) * 2 + 0],
                             b[nf >> 1][(nf & 1) * 2 + 1]);
        }
    }

    const int mbase = bm + wm * 64 + (lane >> 2);
    const int nbase = bn + wn * 64 + (lane & 3) * 2;
#pragma unroll
    for (int mf = 0; mf < 4; mf++) {
#pragma unroll
        for (int nf = 0; nf < 8; nf++) {
            const int c = nbase + nf * 8;
            const float bi0 = __ldg(bias + c);
            const float bi1 = __ldg(bias + c + 1);
            const int r0 = mbase + mf * 16;
            *(float2*)(C + (size_t)r0 * Ntot + c) =
                make_float2(acc[mf][nf][0] + bi0, acc[mf][nf][1] + bi1);
            *(float2*)(C + (size_t)(r0 + 8) * Ntot + c) =
                make_float2(acc[mf][nf][2] + bi0, acc[mf][nf][3] + bi1);
        }
    }
}

// ---------------------------------------------------------------------------
// bf16x3 GEMM, CTA 128x128, warp tile 32x64 (projection; verified round 4)
// ---------------------------------------------------------------------------
#define STAGEB (128 * GSTR * 2)
#define PRJ_DSMEM (NSTAGE * 2 * STAGEB)

__global__ __launch_bounds__(256, 2)
void gemm_prj(const __nv_bfloat16* __restrict__ Ahi,
              const __nv_bfloat16* __restrict__ Alo,
              const __nv_bfloat16* __restrict__ Bhi,
              const __nv_bfloat16* __restrict__ Blo,
              const float* __restrict__ bias,
              float* __restrict__ C, int Ntot) {
    extern __shared__ __nv_bfloat16 sm[];
    const uint32_t sbase = smem_u32(sm);

    const int tid  = threadIdx.x;
    const int lane = tid & 31;
    const int warp = tid >> 5;
    const int wm   = warp & 3;
    const int wn   = warp >> 2;
    const int bm   = blockIdx.y * 128;
    const int bn   = blockIdx.x * 128;

    const int lrow = tid >> 1;
    const int lc0  = (tid & 1) * 2;

    const int q2 = lane >> 3;
    const int lr = lane & 7;
    const int aMrow = wm * 32 + (q2 & 1) * 8 + lr;
    const int aKoff = (q2 >> 1) * 8;
    const int bNrow = wn * 64 + (q2 >> 1) * 8 + lr;
    const int bKoff = (q2 & 1) * 8;

    float acc[2][8][4];
#pragma unroll
    for (int i = 0; i < 2; i++)
#pragma unroll
        for (int j = 0; j < 8; j++)
#pragma unroll
            for (int r = 0; r < 4; r++) acc[i][j][r] = 0.0f;

    auto issue = [&](int it, int s) {
        const int seg  = it >> 6;
        const int kloc = (it & 63) * 32;
        const __nv_bfloat16* Asrc = (seg < 2) ? Ahi : Alo;
        const __nv_bfloat16* Bsrc = (seg == 1) ? Blo : Bhi;
        const uint32_t ab = sbase + (uint32_t)s * (2 * STAGEB);
        const uint32_t bb = ab + STAGEB;
#pragma unroll
        for (int j = 0; j < 2; j++) {
            const int c = lc0 + j;
            cp16(ab + (uint32_t)(lrow * GSTR + c * 8) * 2,
                 Asrc + (size_t)(bm + lrow) * KDIM + kloc + c * 8);
            cp16(bb + (uint32_t)(lrow * GSTR + c * 8) * 2,
                 Bsrc + (size_t)(bn + lrow) * KDIM + kloc + c * 8);
        }
    };

#pragma unroll
    for (int s = 0; s < NSTAGE - 1; s++) {
        issue(s, s);
        CP_COMMIT();
    }

    for (int it = 0; it < GITERS; it++) {
        CP_WAIT(NSTAGE - 2);
        __syncthreads();
        if (it + NSTAGE - 1 < GITERS) issue(it + NSTAGE - 1, (it + NSTAGE - 1) % NSTAGE);
        CP_COMMIT();

        const int s = it % NSTAGE;
        const uint32_t sAb = sbase + (uint32_t)s * (2 * STAGEB);
        const uint32_t sBb = sAb + STAGEB;
#pragma unroll
        for (int q = 0; q < 2; q++) {
            uint32_t a[2][4];
#pragma unroll
            for (int mf = 0; mf < 2; mf++)
                ldm_x4(sAb + (uint32_t)(((aMrow + mf * 16) * GSTR + q * 16 + aKoff) * 2),
                       a[mf][0], a[mf][1], a[mf][2], a[mf][3]);
            uint32_t b[4][4];
#pragma unroll
            for (int p = 0; p < 4; p++)
                ldm_x4(sBb + (uint32_t)(((bNrow + p * 16) * GSTR + q * 16 + bKoff) * 2),
                       b[p][0], b[p][1], b[p][2], b[p][3]);
#pragma unroll
            for (int mf = 0; mf < 2; mf++)
#pragma unroll
                for (int nf = 0; nf < 8; nf++)
                    mma16816(acc[mf][nf], a[mf],
                             b[nf >> 1][(nf & 1) * 2 + 0],
                             b[nf >> 1][(nf & 1) * 2 + 1]);
        }
    }

    const int mbase = bm + wm * 32 + (lane >> 2);
    const int nbase = bn + wn * 64 + (lane & 3) * 2;
#pragma unroll
    for (int mf = 0; mf < 2; mf++) {
#pragma unroll
        for (int nf = 0; nf < 8; nf++) {
            const int c = nbase + nf * 8;
            const float bi0 = __ldg(bias + c);
            const float bi1 = __ldg(bias + c + 1);
            const int r0 = mbase + mf * 16;
            *(float2*)(C + (size_t)r0 * Ntot + c) =
                make_float2(acc[mf][nf][0] + bi0, acc[mf][nf][1] + bi1);
            *(float2*)(C + (size_t)(r0 + 8) * Ntot + c) =
                make_float2(acc[mf][nf][2] + bi0, acc[mf][nf][3] + bi1);
        }
    }
}

// ---------------------------------------------------------------------------
// Highway combine + fused bf16 hi/lo split of new h
// ---------------------------------------------------------------------------
__global__ __launch_bounds__(256)
void highway_kernel(const float* __restrict__ p, float* __restrict__ h,
                    __nv_bfloat16* __restrict__ hhi,
                    __nv_bfloat16* __restrict__ hlo) {
    int idx = blockIdx.x * blockDim.x + threadIdx.x;
    int total = NTOK * (NFILT / 4);
    if (idx >= total) return;
    int m  = idx / (NFILT / 4);
    int j4 = idx % (NFILT / 4);

    const float4 pt = *(const float4*)(p + (size_t)m * (2 * NFILT) + j4 * 4);
    const float4 pg = *(const float4*)(p + (size_t)m * (2 * NFILT) + NFILT + j4 * 4);
    float4 hv = *(float4*)(h + (size_t)m * NFILT + j4 * 4);

    float g;
    g = 1.0f / (1.0f + expf(-pg.x)); hv.x = g * hv.x + (1.0f - g) * fmaxf(pt.x, 0.0f);
    g = 1.0f / (1.0f + expf(-pg.y)); hv.y = g * hv.y + (1.0f - g) * fmaxf(pt.y, 0.0f);
    g = 1.0f / (1.0f + expf(-pg.z)); hv.z = g * hv.z + (1.0f - g) * fmaxf(pt.z, 0.0f);
    g = 1.0f / (1.0f + expf(-pg.w)); hv.w = g * hv.w + (1.0f - g) * fmaxf(pt.w, 0.0f);

    *(float4*)(h + (size_t)m * NFILT + j4 * 4) = hv;

    __nv_bfloat16 h0 = __float2bfloat16(hv.x);
    __nv_bfloat16 h1 = __float2bfloat16(hv.y);
    __nv_bfloat16 h2 = __float2bfloat16(hv.z);
    __nv_bfloat16 h3 = __float2bfloat16(hv.w);
    __nv_bfloat162* hp = (__nv_bfloat162*)(hhi + (size_t)m * NFILT + j4 * 4);
    __nv_bfloat162* lp = (__nv_bfloat162*)(hlo + (size_t)m * NFILT + j4 * 4);
    hp[0] = __halves2bfloat162(h0, h1);
    hp[1] = __halves2bfloat162(h2, h3);
    lp[0] = __halves2bfloat162(__float2bfloat16(hv.x - __bfloat162float(h0)),
                               __float2bfloat16(hv.y - __bfloat162float(h1)));
    lp[1] = __halves2bfloat162(__float2bfloat16(hv.z - __bfloat162float(h2)),
                               __float2bfloat16(hv.w - __bfloat162float(h3)));
}

// ---------------------------------------------------------------------------
// Launch
// ---------------------------------------------------------------------------
extern "C" void kernel_launch(void* const* d_in, const int* in_sizes, int n_in,
                              void* d_out, int out_size) {
    const int*   chars  = (const int*)d_in[1];
    const float* emb    = (const float*)d_in[2];
    const float* cw[7], *cb[7];
    for (int i = 0; i < 7; i++) {
        cw[i] = (const float*)d_in[3 + 2 * i];
        cb[i] = (const float*)d_in[4 + 2 * i];
    }
    const float* hw_w0  = (const float*)d_in[17];
    const float* hw_b0  = (const float*)d_in[18];
    const float* hw_w1  = (const float*)d_in[19];
    const float* hw_b1  = (const float*)d_in[20];
    const float* proj_w = (const float*)d_in[21];
    const float* proj_b = (const float*)d_in[22];
    float* out = (float*)d_out;

    static float *hbuf = nullptr, *pbuf = nullptr, *wtbuf = nullptr;
    static __nv_bfloat16 *hhi, *hlo, *w0hi, *w0lo, *w1hi, *w1lo, *wphi, *wplo;
    if (!hbuf) {
        cudaGetSymbolAddress((void**)&hbuf,  g_h);
        cudaGetSymbolAddress((void**)&pbuf,  g_p);
        cudaGetSymbolAddress((void**)&wtbuf, g_wt);
        cudaGetSymbolAddress((void**)&hhi,   g_hhi);
        cudaGetSymbolAddress((void**)&hlo,   g_hlo);
        cudaGetSymbolAddress((void**)&w0hi,  g_w0hi);
        cudaGetSymbolAddress((void**)&w0lo,  g_w0lo);
        cudaGetSymbolAddress((void**)&w1hi,  g_w1hi);
        cudaGetSymbolAddress((void**)&w1lo,  g_w1lo);
        cudaGetSymbolAddress((void**)&wphi,  g_wphi);
        cudaGetSymbolAddress((void**)&wplo,  g_wplo);
        cudaFuncSetAttribute(gemm_big,
                             cudaFuncAttributeMaxDynamicSharedMemorySize,
                             BIG_DSMEM);
        cudaFuncSetAttribute(gemm_prj,
                             cudaFuncAttributeMaxDynamicSharedMemorySize,
                             PRJ_DSMEM);
    }

    dim3 blk(256);
    const int nW  = 2 * NFILT * NFILT;
    const int nWP = PROJ * NFILT;
    auto cvb = [](int n) { return (n / 4 + 255) / 256; };

    const int wt_off[7] = {WT_O0, WT_O1, WT_O2, WT_O3, WT_O4, WT_O5, WT_O6};
    const int wt_nf[7]  = {32, 32, 64, 128, 256, 512, 1024};
    for (int i = 0; i < 7; i++) {
        int cw_i = CDIM * (i + 1);
        int tot  = wt_nf[i] * cw_i;
        transpose_w<<<(tot + 255) / 256, blk>>>(cw[i], wtbuf + wt_off[i],
                                                wt_nf[i], cw_i);
    }

    cvt_split<<<cvb(nW),  blk>>>(hw_w0,  w0hi, w0lo, nW / 4);
    cvt_split<<<cvb(nW),  blk>>>(hw_w1,  w1hi, w1lo, nW / 4);
    cvt_split<<<cvb(nWP), blk>>>(proj_w, wphi, wplo, nWP / 4);

    // 1) conv (writes h + hi/lo split)
    conv_kernel<<<NTOK, 256>>>(chars, emb, wtbuf,
                               cb[0], cb[1], cb[2], cb[3], cb[4], cb[5], cb[6],
                               hbuf, hhi, hlo);

    dim3 grid_hw(2 * NFILT / 256, NTOK / 128);   // (16, 32)
    dim3 grid_pr(PROJ / 128, NTOK / 128);        // (4, 32)
    int hw_blocks = (NTOK * (NFILT / 4) + 255) / 256;

    // 2-3) highway layer 0
    gemm_big<<<grid_hw, blk, BIG_DSMEM>>>(hhi, hlo, w0hi, w0lo, hw_b0,
                                          pbuf, 2 * NFILT);
    highway_kernel<<<hw_blocks, blk>>>(pbuf, hbuf, hhi, hlo);

    // 4-5) highway layer 1
    gemm_big<<<grid_hw, blk, BIG_DSMEM>>>(hhi, hlo, w1hi, w1lo, hw_b1,
                                          pbuf, 2 * NFILT);
    highway_kernel<<<hw_blocks, blk>>>(pbuf, hbuf, hhi, hlo);

    // 6) projection
    gemm_prj<<<grid_pr, blk, PRJ_DSMEM>>>(hhi, hlo, wphi, wplo, proj_b,
                                          out, PROJ);
}